// round 15
// baseline (speedup 1.0000x reference)
#include <cuda_runtime.h>
#include <cuda_fp16.h>
#include <mma.h>
#include <cstdint>

using namespace nvcuda;

#define N_MAX 50000
#define N_PAD 50048
#define E_MAX 800000
#define C 64
#define FIN 128
#define D 192
#define NEG_SLOPE 0.2f
#define SCAN_B 512

// ---------------- scratch (static __device__; no allocations allowed) -------
__device__ __align__(16) __half g_hzr[N_MAX * 128];  // interleaved: [z2p,z2p+1,r2p,r2p+1]
__device__ __align__(16) __half g_hh[N_MAX * C];
__device__ __align__(16) __half g_HR[N_MAX * C];
__device__ __align__(16) float g_hhp[N_PAD * C];     // X@Wh[0:128] fp32 partial
__device__ __align__(16) float g_Z[N_MAX * C];
__device__ float g_als_z[N_MAX], g_ald_z[N_MAX];
__device__ float g_als_r[N_MAX], g_ald_r[N_MAX];
__device__ float g_als_h[N_MAX], g_ald_h[N_MAX];
__device__ int g_cnt[N_MAX];        // zero at start; re-zeroed by k_scan3
__device__ int g_rs[N_MAX + 1];
__device__ int g_cur[N_MAX];
__device__ int g_bsum[512], g_boff[512];
__device__ int g_csrc[E_MAX];
__device__ int g_cdst[E_MAX];
__device__ uint32_t g_ewzr[E_MAX];   // half2 {ez, er}
__device__ __half g_ewh[E_MAX];

// ---------------- helpers ----------------
__device__ __forceinline__ float lrelu(float x) { return x > 0.f ? x : NEG_SLOPE * x; }
__device__ __forceinline__ float sigmoidf_(float x) { return 1.f / (1.f + __expf(-x)); }

// ================= CSR build (g_cnt self-cleaning) =================
__global__ void k_count(const int* __restrict__ dst, int E) {
    int e = blockIdx.x * blockDim.x + threadIdx.x;
    if (e < E) atomicAdd(&g_cnt[dst[e]], 1);
}
__global__ void k_scan1(int n) {
    __shared__ int sm[SCAN_B];
    int i = blockIdx.x * SCAN_B + threadIdx.x;
    int c = (i < n) ? g_cnt[i] : 0;
    sm[threadIdx.x] = c;
    __syncthreads();
    for (int off = SCAN_B / 2; off; off >>= 1) {
        if (threadIdx.x < off) sm[threadIdx.x] += sm[threadIdx.x + off];
        __syncthreads();
    }
    if (threadIdx.x == 0) g_bsum[blockIdx.x] = sm[0];
}
__global__ void k_scan2(int nb, int n) {
    __shared__ int sm[512];
    int t = threadIdx.x;
    int v = (t < nb) ? g_bsum[t] : 0;
    sm[t] = v;
    __syncthreads();
    for (int off = 1; off < 512; off <<= 1) {
        int u = (t >= off) ? sm[t - off] : 0;
        __syncthreads();
        sm[t] += u;
        __syncthreads();
    }
    if (t < nb) g_boff[t] = sm[t] - v;
    if (t == 511) g_rs[n] = sm[511];
}
__global__ void k_scan3(int n) {
    __shared__ int sm[SCAN_B];
    int t = threadIdx.x;
    int i = blockIdx.x * SCAN_B + t;
    int c = (i < n) ? g_cnt[i] : 0;
    sm[t] = c;
    __syncthreads();
    for (int off = 1; off < SCAN_B; off <<= 1) {
        int v = (t >= off) ? sm[t - off] : 0;
        __syncthreads();
        sm[t] += v;
        __syncthreads();
    }
    if (i < n) {
        int excl = g_boff[blockIdx.x] + sm[t] - c;
        g_rs[i] = excl;
        g_cur[i] = excl;
        g_cnt[i] = 0;      // restore zero for the next invocation
    }
}
__global__ void k_scatter(const int* __restrict__ src, const int* __restrict__ dst, int E) {
    int e = blockIdx.x * blockDim.x + threadIdx.x;
    if (e < E) {
        int d = dst[e];
        int pos = atomicAdd(&g_cur[d], 1);
        g_csrc[pos] = src[e];
        g_cdst[pos] = d;
    }
}

// ================= edge weights (CSR-slot-parallel) =================
__global__ void ew_zr(int E) {
    int i = blockIdx.x * blockDim.x + threadIdx.x;
    if (i >= E) return;
    int s = g_csrc[i], d = g_cdst[i];
    float ez = __expf(lrelu(g_als_z[s] + g_ald_z[d]));
    float er = __expf(lrelu(g_als_r[s] + g_ald_r[d]));
    __half2 p = __floats2half2_rn(ez, er);
    g_ewzr[i] = *(uint32_t*)&p;
}
__global__ void ew_h(int E) {
    int i = blockIdx.x * blockDim.x + threadIdx.x;
    if (i >= E) return;
    int s = g_csrc[i], d = g_cdst[i];
    g_ewh[i] = __float2half(__expf(lrelu(g_als_h[s] + g_ald_h[d])));
}

// ================= fp16 wmma GEMMs =================
#define AH_LD 24
#define BH_LD_ZR 136
#define BH_LD_H 72
#define CS_LD_ZR 132
#define CS_LD_H 68

// gemm_zr: BM=128, BN=128 (z|r interleaved pairs); 8 warps as 4x2 (warp tile
// 32x64, 8 MMAs/warp/iter); register-prefetch pipeline; two-pass epilogue with
// fused als/ald computation.
__global__ void __launch_bounds__(256)
gemm_zr(const float* __restrict__ A1, const float* __restrict__ A2,
        const float* __restrict__ B1, const float* __restrict__ B2,
        const float* __restrict__ az_s, const float* __restrict__ az_d,
        const float* __restrict__ ar_s, const float* __restrict__ ar_d, int n)
{
    __shared__ __half Ah[128 * AH_LD];      // 6 KB
    __shared__ __half Bh[16 * BH_LD_ZR];    // 4.25 KB
    __shared__ float Cs[64 * CS_LD_ZR];     // 33.8 KB (two-pass)

    int tid = threadIdx.x, warp = tid >> 5;
    int warp_m = warp >> 1, warp_n = warp & 1;   // 4 x 2; rows warp_m*32, cols warp_n*64
    int row0 = blockIdx.x * 128;

    wmma::fragment<wmma::accumulator, 16, 16, 16, float> acc[2][4];
#pragma unroll
    for (int mi = 0; mi < 2; mi++)
#pragma unroll
        for (int j = 0; j < 4; j++) wmma::fill_fragment(acc[mi][j], 0.f);

    int a_row = tid >> 1;            // 0..127
    int a_kg = (tid & 1) * 8;        // 0 or 8
    int b_kk = tid >> 4;             // 0..15
    int b_q = tid & 15;
    int grow = row0 + a_row;

    float4 pa0, pa1, pbz, pbr;

#define LOADT(K0)                                                              \
    {                                                                          \
        int k = (K0) + a_kg;                                                   \
        pa0 = make_float4(0.f, 0.f, 0.f, 0.f);                                 \
        pa1 = pa0;                                                             \
        if (grow < n) {                                                        \
            if (k < FIN) {                                                     \
                pa0 = *(const float4*)(A1 + (size_t)grow * FIN + k);           \
                pa1 = *(const float4*)(A1 + (size_t)grow * FIN + k + 4);       \
            } else {                                                           \
                pa0 = *(const float4*)(A2 + (size_t)grow * C + (k - FIN));     \
                pa1 = *(const float4*)(A2 + (size_t)grow * C + (k - FIN) + 4); \
            }                                                                  \
        }                                                                      \
        pbz = *(const float4*)(B1 + (size_t)((K0) + b_kk) * C + b_q * 4);      \
        pbr = *(const float4*)(B2 + (size_t)((K0) + b_kk) * C + b_q * 4);      \
    }
#define STORET()                                                               \
    {                                                                          \
        __half2* pap = (__half2*)(Ah + a_row * AH_LD + a_kg);                  \
        pap[0] = __floats2half2_rn(pa0.x, pa0.y);                              \
        pap[1] = __floats2half2_rn(pa0.z, pa0.w);                              \
        pap[2] = __floats2half2_rn(pa1.x, pa1.y);                              \
        pap[3] = __floats2half2_rn(pa1.z, pa1.w);                              \
        __half2* pbp = (__half2*)(Bh + b_kk * BH_LD_ZR + b_q * 8);             \
        pbp[0] = __floats2half2_rn(pbz.x, pbz.y);                              \
        pbp[1] = __floats2half2_rn(pbr.x, pbr.y);                              \
        pbp[2] = __floats2half2_rn(pbz.z, pbz.w);                              \
        pbp[3] = __floats2half2_rn(pbr.z, pbr.w);                              \
    }

    LOADT(0);
    STORET();
    __syncthreads();

    const int nIt = D / 16;  // 12
    for (int it = 0; it < nIt; it++) {
        if (it + 1 < nIt) LOADT((it + 1) * 16);

        wmma::fragment<wmma::matrix_a, 16, 16, 16, __half, wmma::row_major> fa;
#pragma unroll
        for (int mi = 0; mi < 2; mi++) {
            wmma::load_matrix_sync(fa, Ah + (warp_m * 32 + mi * 16) * AH_LD, AH_LD);
#pragma unroll
            for (int j = 0; j < 4; j++) {
                wmma::fragment<wmma::matrix_b, 16, 16, 16, __half, wmma::row_major> fb;
                wmma::load_matrix_sync(fb, Bh + warp_n * 64 + j * 16, BH_LD_ZR);
                wmma::mma_sync(acc[mi][j], fa, fb, acc[mi][j]);
            }
        }
        __syncthreads();
        if (it + 1 < nIt) {
            STORET();
            __syncthreads();
        }
    }
#undef LOADT
#undef STORET

    // two-pass epilogue: rows [0,64) then [64,128)
#pragma unroll
    for (int p = 0; p < 2; p++) {
        if ((warp >> 2) == p) {
            int lm = (warp_m & 1) * 32;
#pragma unroll
            for (int mi = 0; mi < 2; mi++)
#pragma unroll
                for (int j = 0; j < 4; j++)
                    wmma::store_matrix_sync(Cs + (lm + mi * 16) * CS_LD_ZR + warp_n * 64 + j * 16,
                                            acc[mi][j], CS_LD_ZR, wmma::mem_row_major);
        }
        __syncthreads();
        {
            int r = tid >> 2;
            int grow2 = row0 + p * 64 + r;
            float sz = 0.f, dz = 0.f, sr = 0.f, dr = 0.f;
#pragma unroll
            for (int qq = 0; qq < 4; qq++) {
                int q = (tid & 3) * 4 + qq;
                float4 f0 = *(const float4*)(Cs + r * CS_LD_ZR + 8 * q);
                float4 f1 = *(const float4*)(Cs + r * CS_LD_ZR + 8 * q + 4);
                sz += f0.x * __ldg(az_s + 4 * q) + f0.y * __ldg(az_s + 4 * q + 1)
                    + f1.x * __ldg(az_s + 4 * q + 2) + f1.y * __ldg(az_s + 4 * q + 3);
                dz += f0.x * __ldg(az_d + 4 * q) + f0.y * __ldg(az_d + 4 * q + 1)
                    + f1.x * __ldg(az_d + 4 * q + 2) + f1.y * __ldg(az_d + 4 * q + 3);
                sr += f0.z * __ldg(ar_s + 4 * q) + f0.w * __ldg(ar_s + 4 * q + 1)
                    + f1.z * __ldg(ar_s + 4 * q + 2) + f1.w * __ldg(ar_s + 4 * q + 3);
                dr += f0.z * __ldg(ar_d + 4 * q) + f0.w * __ldg(ar_d + 4 * q + 1)
                    + f1.z * __ldg(ar_d + 4 * q + 2) + f1.w * __ldg(ar_d + 4 * q + 3);
                if (grow2 < n) {
                    __half2 h0 = __floats2half2_rn(f0.x, f0.y);
                    __half2 h1 = __floats2half2_rn(f0.z, f0.w);
                    __half2 h2 = __floats2half2_rn(f1.x, f1.y);
                    __half2 h3 = __floats2half2_rn(f1.z, f1.w);
                    uint4 pk;
                    pk.x = *(uint32_t*)&h0; pk.y = *(uint32_t*)&h1;
                    pk.z = *(uint32_t*)&h2; pk.w = *(uint32_t*)&h3;
                    *(uint4*)(g_hzr + (size_t)grow2 * 128 + 8 * q) = pk;
                }
            }
            sz += __shfl_xor_sync(0xffffffffu, sz, 1);
            sz += __shfl_xor_sync(0xffffffffu, sz, 2);
            dz += __shfl_xor_sync(0xffffffffu, dz, 1);
            dz += __shfl_xor_sync(0xffffffffu, dz, 2);
            sr += __shfl_xor_sync(0xffffffffu, sr, 1);
            sr += __shfl_xor_sync(0xffffffffu, sr, 2);
            dr += __shfl_xor_sync(0xffffffffu, dr, 1);
            dr += __shfl_xor_sync(0xffffffffu, dr, 2);
            if ((tid & 3) == 0 && grow2 < n) {
                g_als_z[grow2] = sz; g_ald_z[grow2] = dz;
                g_als_r[grow2] = sr; g_ald_r[grow2] = dr;
            }
        }
        __syncthreads();
    }
}

// gemm_hx: X (n x 128) @ Wh[0:128] -> fp32 partial g_hhp (side stream).
__global__ void __launch_bounds__(256)
gemm_hx(const float* __restrict__ A1, const float* __restrict__ B1, int n)
{
    __shared__ __half Ah[64 * AH_LD];
    __shared__ __half Bh[16 * BH_LD_H];

    int tid = threadIdx.x, warp = tid >> 5;
    int warp_m = warp >> 1, warp_n = warp & 1;
    int row0 = blockIdx.x * 64;

    wmma::fragment<wmma::accumulator, 16, 16, 16, float> acc[2];
#pragma unroll
    for (int j = 0; j < 2; j++) wmma::fill_fragment(acc[j], 0.f);

    int a_row = tid >> 2;
    int a_kg = (tid & 3) * 4;
    int b_kk = tid >> 4;
    int b_col = (tid & 15) * 4;
    int grow = row0 + a_row;

    for (int k0 = 0; k0 < FIN; k0 += 16) {
        {
            float4 v = make_float4(0.f, 0.f, 0.f, 0.f);
            if (grow < n) v = *(const float4*)(A1 + (size_t)grow * FIN + k0 + a_kg);
            __half2* pa = (__half2*)(Ah + a_row * AH_LD + a_kg);
            pa[0] = __floats2half2_rn(v.x, v.y);
            pa[1] = __floats2half2_rn(v.z, v.w);
        }
        {
            float4 v = *(const float4*)(B1 + (size_t)(k0 + b_kk) * C + b_col);
            __half2* pb = (__half2*)(Bh + b_kk * BH_LD_H + b_col);
            pb[0] = __floats2half2_rn(v.x, v.y);
            pb[1] = __floats2half2_rn(v.z, v.w);
        }
        __syncthreads();

        wmma::fragment<wmma::matrix_a, 16, 16, 16, __half, wmma::row_major> fa;
        wmma::load_matrix_sync(fa, Ah + warp_m * 16 * AH_LD, AH_LD);
#pragma unroll
        for (int j = 0; j < 2; j++) {
            wmma::fragment<wmma::matrix_b, 16, 16, 16, __half, wmma::row_major> fb;
            wmma::load_matrix_sync(fb, Bh + warp_n * 32 + j * 16, BH_LD_H);
            wmma::mma_sync(acc[j], fa, fb, acc[j]);
        }
        __syncthreads();
    }
#pragma unroll
    for (int j = 0; j < 2; j++)
        wmma::store_matrix_sync(g_hhp + (size_t)(row0 + warp_m * 16) * C + warp_n * 32 + j * 16,
                                acc[j], C, wmma::mem_row_major);
}

// gemm_hhr: g_HR @ Wh[128:192] + g_hhp -> g_hh; epilogue computes als_h/ald_h.
__global__ void __launch_bounds__(256)
gemm_hhr(const float* __restrict__ B1,
         const float* __restrict__ ah_s, const float* __restrict__ ah_d, int n)
{
    __shared__ __half Ah[64 * AH_LD];
    __shared__ __half Bh[16 * BH_LD_H];
    __shared__ float Cs[64 * CS_LD_H];

    int tid = threadIdx.x, warp = tid >> 5;
    int warp_m = warp >> 1, warp_n = warp & 1;
    int row0 = blockIdx.x * 64;

    wmma::fragment<wmma::accumulator, 16, 16, 16, float> acc[2];
#pragma unroll
    for (int j = 0; j < 2; j++) wmma::fill_fragment(acc[j], 0.f);

    int a_row = tid >> 2;
    int a_kg = (tid & 3) * 4;
    int b_kk = tid >> 4;
    int b_col = (tid & 15) * 4;
    int grow = row0 + a_row;

    for (int k0 = 0; k0 < C; k0 += 16) {
        {
            uint2 raw = make_uint2(0u, 0u);
            if (grow < n) raw = *(const uint2*)(g_HR + (size_t)grow * C + k0 + a_kg);
            __half2* pa = (__half2*)(Ah + a_row * AH_LD + a_kg);
            pa[0] = *(__half2*)&raw.x;
            pa[1] = *(__half2*)&raw.y;
        }
        {
            float4 v = *(const float4*)(B1 + (size_t)(FIN + k0 + b_kk) * C + b_col);
            __half2* pb = (__half2*)(Bh + b_kk * BH_LD_H + b_col);
            pb[0] = __floats2half2_rn(v.x, v.y);
            pb[1] = __floats2half2_rn(v.z, v.w);
        }
        __syncthreads();

        wmma::fragment<wmma::matrix_a, 16, 16, 16, __half, wmma::row_major> fa;
        wmma::load_matrix_sync(fa, Ah + warp_m * 16 * AH_LD, AH_LD);
#pragma unroll
        for (int j = 0; j < 2; j++) {
            wmma::fragment<wmma::matrix_b, 16, 16, 16, __half, wmma::row_major> fb;
            wmma::load_matrix_sync(fb, Bh + warp_n * 32 + j * 16, BH_LD_H);
            wmma::mma_sync(acc[j], fa, fb, acc[j]);
        }
        __syncthreads();
    }

#pragma unroll
    for (int j = 0; j < 2; j++)
        wmma::store_matrix_sync(Cs + warp_m * 16 * CS_LD_H + warp_n * 32 + j * 16,
                                acc[j], CS_LD_H, wmma::mem_row_major);
    __syncthreads();
    {
        int r = tid >> 2, c0 = (tid & 3) * 16;
        int grow2 = row0 + r;
        float s = 0.f, d = 0.f;
#pragma unroll
        for (int c = 0; c < 16; c += 8) {
            float4 f0 = *(const float4*)(Cs + r * CS_LD_H + c0 + c);
            float4 f1 = *(const float4*)(Cs + r * CS_LD_H + c0 + c + 4);
            float4 p0 = make_float4(0.f, 0.f, 0.f, 0.f), p1 = p0;
            if (grow2 < n) {
                p0 = *(const float4*)(g_hhp + (size_t)grow2 * C + c0 + c);
                p1 = *(const float4*)(g_hhp + (size_t)grow2 * C + c0 + c + 4);
            }
            float v0 = f0.x + p0.x, v1 = f0.y + p0.y, v2 = f0.z + p0.z, v3 = f0.w + p0.w;
            float v4 = f1.x + p1.x, v5 = f1.y + p1.y, v6 = f1.z + p1.z, v7 = f1.w + p1.w;
            int cc = c0 + c;
            s += v0 * __ldg(ah_s + cc) + v1 * __ldg(ah_s + cc + 1)
               + v2 * __ldg(ah_s + cc + 2) + v3 * __ldg(ah_s + cc + 3)
               + v4 * __ldg(ah_s + cc + 4) + v5 * __ldg(ah_s + cc + 5)
               + v6 * __ldg(ah_s + cc + 6) + v7 * __ldg(ah_s + cc + 7);
            d += v0 * __ldg(ah_d + cc) + v1 * __ldg(ah_d + cc + 1)
               + v2 * __ldg(ah_d + cc + 2) + v3 * __ldg(ah_d + cc + 3)
               + v4 * __ldg(ah_d + cc + 4) + v5 * __ldg(ah_d + cc + 5)
               + v6 * __ldg(ah_d + cc + 6) + v7 * __ldg(ah_d + cc + 7);
            if (grow2 < n) {
                __half2 h0 = __floats2half2_rn(v0, v1);
                __half2 h1 = __floats2half2_rn(v2, v3);
                __half2 h2 = __floats2half2_rn(v4, v5);
                __half2 h3 = __floats2half2_rn(v6, v7);
                uint4 pk;
                pk.x = *(uint32_t*)&h0; pk.y = *(uint32_t*)&h1;
                pk.z = *(uint32_t*)&h2; pk.w = *(uint32_t*)&h3;
                *(uint4*)(g_hh + (size_t)grow2 * C + cc) = pk;
            }
        }
        s += __shfl_xor_sync(0xffffffffu, s, 1);
        s += __shfl_xor_sync(0xffffffffu, s, 2);
        d += __shfl_xor_sync(0xffffffffu, d, 1);
        d += __shfl_xor_sync(0xffffffffu, d, 2);
        if ((tid & 3) == 0 && grow2 < n) { g_als_h[grow2] = s; g_ald_h[grow2] = d; }
    }
}

// ================= fused per-dst accumulation (unroll-4) =====================
__global__ void zr_node(const float* __restrict__ H,
                        const float* __restrict__ bz, const float* __restrict__ br, int n)
{
    int d = (blockIdx.x * blockDim.x + threadIdx.x) >> 5;
    if (d >= n) return;
    int l = threadIdx.x & 31;

    float ez = 0.f, er = 0.f;
    if (l == 0)  ez = __expf(lrelu(g_als_z[d] + g_ald_z[d]));
    if (l == 16) er = __expf(lrelu(g_als_r[d] + g_ald_r[d]));
    ez = __shfl_sync(0xffffffffu, ez, 0);
    er = __shfl_sync(0xffffffffu, er, 16);

    uint2 raw = *(const uint2*)(g_hzr + (size_t)d * 128 + 4 * l);
    float2 vz = __half22float2(*(__half2*)&raw.x);
    float2 vr = __half22float2(*(__half2*)&raw.y);
    float az0 = vz.x * ez, az1 = vz.y * ez;
    float ar0 = vr.x * er, ar1 = vr.y * er;
    float denz = ez, denr = er;

    int b = g_rs[d], e_end = g_rs[d + 1];
    int i = b;
    for (; i + 3 < e_end; i += 4) {
        int s0 = g_csrc[i], s1 = g_csrc[i + 1], s2 = g_csrc[i + 2], s3 = g_csrc[i + 3];
        uint32_t w0 = g_ewzr[i], w1 = g_ewzr[i + 1], w2 = g_ewzr[i + 2], w3 = g_ewzr[i + 3];
        uint2 r0 = *(const uint2*)(g_hzr + (size_t)s0 * 128 + 4 * l);
        uint2 r1 = *(const uint2*)(g_hzr + (size_t)s1 * 128 + 4 * l);
        uint2 r2 = *(const uint2*)(g_hzr + (size_t)s2 * 128 + 4 * l);
        uint2 r3 = *(const uint2*)(g_hzr + (size_t)s3 * 128 + 4 * l);
        float2 e0 = __half22float2(*(__half2*)&w0);
        float2 e1 = __half22float2(*(__half2*)&w1);
        float2 e2 = __half22float2(*(__half2*)&w2);
        float2 e3 = __half22float2(*(__half2*)&w3);
        float2 uz0 = __half22float2(*(__half2*)&r0.x), ur0 = __half22float2(*(__half2*)&r0.y);
        float2 uz1 = __half22float2(*(__half2*)&r1.x), ur1 = __half22float2(*(__half2*)&r1.y);
        float2 uz2 = __half22float2(*(__half2*)&r2.x), ur2 = __half22float2(*(__half2*)&r2.y);
        float2 uz3 = __half22float2(*(__half2*)&r3.x), ur3 = __half22float2(*(__half2*)&r3.y);
        az0 += uz0.x * e0.x + uz1.x * e1.x + uz2.x * e2.x + uz3.x * e3.x;
        az1 += uz0.y * e0.x + uz1.y * e1.x + uz2.y * e2.x + uz3.y * e3.x;
        ar0 += ur0.x * e0.y + ur1.x * e1.y + ur2.x * e2.y + ur3.x * e3.y;
        ar1 += ur0.y * e0.y + ur1.y * e1.y + ur2.y * e2.y + ur3.y * e3.y;
        denz += e0.x + e1.x + e2.x + e3.x;
        denr += e0.y + e1.y + e2.y + e3.y;
    }
    for (; i < e_end; i++) {
        int s0 = g_csrc[i];
        uint32_t w0 = g_ewzr[i];
        float2 e0 = __half22float2(*(__half2*)&w0);
        uint2 r0 = *(const uint2*)(g_hzr + (size_t)s0 * 128 + 4 * l);
        float2 uz0 = __half22float2(*(__half2*)&r0.x);
        float2 ur0 = __half22float2(*(__half2*)&r0.y);
        az0 += uz0.x * e0.x; az1 += uz0.y * e0.x;
        ar0 += ur0.x * e0.y; ar1 += ur0.y * e0.y;
        denz += e0.x; denr += e0.y;
    }

    float iz = 1.f / (denz + 1e-16f), ir = 1.f / (denr + 1e-16f);
    float Z0 = sigmoidf_(az0 * iz + __ldg(bz + 2 * l));
    float Z1 = sigmoidf_(az1 * iz + __ldg(bz + 2 * l + 1));
    float R0 = sigmoidf_(ar0 * ir + __ldg(br + 2 * l));
    float R1 = sigmoidf_(ar1 * ir + __ldg(br + 2 * l + 1));
    float2 Hv = *(const float2*)(H + (size_t)d * C + 2 * l);
    *(float2*)(g_Z + (size_t)d * C + 2 * l) = make_float2(Z0, Z1);
    __half2 hr = __floats2half2_rn(Hv.x * R0, Hv.y * R1);
    *(uint32_t*)(g_HR + (size_t)d * C + 2 * l) = *(uint32_t*)&hr;
}

__global__ void h_node(const float* __restrict__ H, const float* __restrict__ bh,
                       float* __restrict__ out, int n)
{
    int d = (blockIdx.x * blockDim.x + threadIdx.x) >> 5;
    if (d >= n) return;
    int l = threadIdx.x & 31;

    float eh = 0.f;
    if (l == 0) eh = __expf(lrelu(g_als_h[d] + g_ald_h[d]));
    eh = __shfl_sync(0xffffffffu, eh, 0);

    uint32_t raw = *(const uint32_t*)(g_hh + (size_t)d * C + 2 * l);
    float2 v = __half22float2(*(__half2*)&raw);
    float a0 = v.x * eh, a1 = v.y * eh;
    float den = eh;

    int b = g_rs[d], e_end = g_rs[d + 1];
    int i = b;
    for (; i + 3 < e_end; i += 4) {
        int s0 = g_csrc[i], s1 = g_csrc[i + 1], s2 = g_csrc[i + 2], s3 = g_csrc[i + 3];
        float eh0 = __half2float(g_ewh[i]);
        float eh1 = __half2float(g_ewh[i + 1]);
        float eh2 = __half2float(g_ewh[i + 2]);
        float eh3 = __half2float(g_ewh[i + 3]);
        uint32_t w0 = *(const uint32_t*)(g_hh + (size_t)s0 * C + 2 * l);
        uint32_t w1 = *(const uint32_t*)(g_hh + (size_t)s1 * C + 2 * l);
        uint32_t w2 = *(const uint32_t*)(g_hh + (size_t)s2 * C + 2 * l);
        uint32_t w3 = *(const uint32_t*)(g_hh + (size_t)s3 * C + 2 * l);
        float2 u0 = __half22float2(*(__half2*)&w0);
        float2 u1 = __half22float2(*(__half2*)&w1);
        float2 u2 = __half22float2(*(__half2*)&w2);
        float2 u3 = __half22float2(*(__half2*)&w3);
        a0 += u0.x * eh0 + u1.x * eh1 + u2.x * eh2 + u3.x * eh3;
        a1 += u0.y * eh0 + u1.y * eh1 + u2.y * eh2 + u3.y * eh3;
        den += eh0 + eh1 + eh2 + eh3;
    }
    for (; i < e_end; i++) {
        int s0 = g_csrc[i];
        float eh0 = __half2float(g_ewh[i]);
        uint32_t w0 = *(const uint32_t*)(g_hh + (size_t)s0 * C + 2 * l);
        float2 u0 = __half22float2(*(__half2*)&w0);
        a0 += u0.x * eh0; a1 += u0.y * eh0;
        den += eh0;
    }

    float inv = 1.f / (den + 1e-16f);
    float ht0 = tanhf(a0 * inv + __ldg(bh + 2 * l));
    float ht1 = tanhf(a1 * inv + __ldg(bh + 2 * l + 1));
    float2 Zv = *(const float2*)(g_Z + (size_t)d * C + 2 * l);
    float2 Hv = *(const float2*)(H + (size_t)d * C + 2 * l);
    float o0 = Zv.x * Hv.x + (1.f - Zv.x) * ht0;
    float o1 = Zv.y * Hv.y + (1.f - Zv.y) * ht1;
    *(float2*)(out + (size_t)d * C + 2 * l) = make_float2(o0, o1);
}

// ---------------- launch ----------------
extern "C" void kernel_launch(void* const* d_in, const int* in_sizes, int n_in,
                              void* d_out, int out_size)
{
    const float* X    = (const float*)d_in[0];
    const int*   ei   = (const int*)  d_in[1];
    const float* H    = (const float*)d_in[2];
    const float* Wz   = (const float*)d_in[3];
    const float* az_s = (const float*)d_in[4];
    const float* az_d = (const float*)d_in[5];
    const float* bz   = (const float*)d_in[6];
    const float* Wr   = (const float*)d_in[7];
    const float* ar_s = (const float*)d_in[8];
    const float* ar_d = (const float*)d_in[9];
    const float* br   = (const float*)d_in[10];
    const float* Wh   = (const float*)d_in[11];
    const float* ah_s = (const float*)d_in[12];
    const float* ah_d = (const float*)d_in[13];
    const float* bh   = (const float*)d_in[14];

    int n = in_sizes[0] / FIN;
    int E = in_sizes[1] / 2;
    const int* src = ei;
    const int* dst = ei + E;

    int nb = (n + SCAN_B - 1) / SCAN_B;
    int gemm_zr_blocks = (n + 127) / 128;
    int gemm_blocks = (n + 63) / 64;
    int warp_blocks = (n * 32 + 255) / 256;
    int eth = (E + 255) / 256;

    static cudaStream_t s_side = nullptr;
    static cudaEvent_t s_fork = nullptr, s_csr = nullptr, s_hx = nullptr;
    if (s_side == nullptr) {
        cudaStreamCreateWithFlags(&s_side, cudaStreamNonBlocking);
        cudaEventCreateWithFlags(&s_fork, cudaEventDisableTiming);
        cudaEventCreateWithFlags(&s_csr, cudaEventDisableTiming);
        cudaEventCreateWithFlags(&s_hx, cudaEventDisableTiming);
    }

    cudaEventRecord(s_fork, 0);
    cudaStreamWaitEvent(s_side, s_fork, 0);

    k_count<<<eth, 256, 0, s_side>>>(dst, E);                 // 0 (side)
    k_scan1<<<nb, SCAN_B, 0, s_side>>>(n);                    // 1 (side)
    k_scan2<<<1, 512, 0, s_side>>>(nb, n);                    // 2 (side)
    gemm_zr<<<gemm_zr_blocks, 256>>>(X, H, Wz, Wr,
                                     az_s, az_d, ar_s, ar_d, n); // 3 (main) <- profiled
    k_scan3<<<nb, SCAN_B, 0, s_side>>>(n);                    // 4 (side)
    k_scatter<<<eth, 256, 0, s_side>>>(src, dst, E);          // 5 (side)
    cudaEventRecord(s_csr, s_side);
    gemm_hx<<<gemm_blocks, 256, 0, s_side>>>(X, Wh, n);       // 6 (side)
    cudaEventRecord(s_hx, s_side);

    cudaStreamWaitEvent(0, s_csr, 0);                         // need CSR + als_zr
    ew_zr<<<eth, 256>>>(E);
    zr_node<<<warp_blocks, 256>>>(H, bz, br, n);

    cudaStreamWaitEvent(0, s_hx, 0);                          // need X@Wh partial
    gemm_hhr<<<gemm_blocks, 256>>>(Wh, ah_s, ah_d, n);
    ew_h<<<eth, 256>>>(E);
    h_node<<<warp_blocks, 256>>>(H, bh, (float*)d_out, n);
}

// round 16
// speedup vs baseline: 1.0314x; 1.0314x over previous
#include <cuda_runtime.h>
#include <cuda_fp16.h>
#include <mma.h>
#include <cstdint>

using namespace nvcuda;

#define N_MAX 50000
#define N_PAD 50048
#define E_MAX 800000
#define C 64
#define FIN 128
#define D 192
#define NEG_SLOPE 0.2f
#define SCAN_B 512

// ---------------- scratch (static __device__; no allocations allowed) -------
__device__ __align__(16) __half g_hzr[N_MAX * 128];  // interleaved: [z2p,z2p+1,r2p,r2p+1]
__device__ __align__(16) __half g_hh[N_MAX * C];
__device__ __align__(16) __half g_HR[N_MAX * C];
__device__ __align__(16) float g_hhp[N_PAD * C];     // X@Wh[0:128] fp32 partial
__device__ __align__(16) float g_Z[N_MAX * C];
__device__ float g_als_z[N_MAX], g_ald_z[N_MAX];
__device__ float g_als_r[N_MAX], g_ald_r[N_MAX];
__device__ float g_als_h[N_MAX], g_ald_h[N_MAX];
__device__ int g_cnt[N_MAX];        // zero at start; re-zeroed by k_scan3
__device__ int g_rs[N_MAX + 1];
__device__ int g_cur[N_MAX];
__device__ int g_bsum[512], g_boff[512];
__device__ int g_csrc[E_MAX];
__device__ int g_cdst[E_MAX];
__device__ uint32_t g_ewzr[E_MAX];   // half2 {ez, er}
__device__ __half g_ewh[E_MAX];

// ---------------- helpers ----------------
__device__ __forceinline__ float lrelu(float x) { return x > 0.f ? x : NEG_SLOPE * x; }
__device__ __forceinline__ float sigmoidf_(float x) { return 1.f / (1.f + __expf(-x)); }

// ================= CSR build (g_cnt self-cleaning) =================
__global__ void k_count(const int* __restrict__ dst, int E) {
    int e = blockIdx.x * blockDim.x + threadIdx.x;
    if (e < E) atomicAdd(&g_cnt[dst[e]], 1);
}
__global__ void k_scan1(int n) {
    __shared__ int sm[SCAN_B];
    int i = blockIdx.x * SCAN_B + threadIdx.x;
    int c = (i < n) ? g_cnt[i] : 0;
    sm[threadIdx.x] = c;
    __syncthreads();
    for (int off = SCAN_B / 2; off; off >>= 1) {
        if (threadIdx.x < off) sm[threadIdx.x] += sm[threadIdx.x + off];
        __syncthreads();
    }
    if (threadIdx.x == 0) g_bsum[blockIdx.x] = sm[0];
}
__global__ void k_scan2(int nb, int n) {
    __shared__ int sm[512];
    int t = threadIdx.x;
    int v = (t < nb) ? g_bsum[t] : 0;
    sm[t] = v;
    __syncthreads();
    for (int off = 1; off < 512; off <<= 1) {
        int u = (t >= off) ? sm[t - off] : 0;
        __syncthreads();
        sm[t] += u;
        __syncthreads();
    }
    if (t < nb) g_boff[t] = sm[t] - v;
    if (t == 511) g_rs[n] = sm[511];
}
__global__ void k_scan3(int n) {
    __shared__ int sm[SCAN_B];
    int t = threadIdx.x;
    int i = blockIdx.x * SCAN_B + t;
    int c = (i < n) ? g_cnt[i] : 0;
    sm[t] = c;
    __syncthreads();
    for (int off = 1; off < SCAN_B; off <<= 1) {
        int v = (t >= off) ? sm[t - off] : 0;
        __syncthreads();
        sm[t] += v;
        __syncthreads();
    }
    if (i < n) {
        int excl = g_boff[blockIdx.x] + sm[t] - c;
        g_rs[i] = excl;
        g_cur[i] = excl;
        g_cnt[i] = 0;      // restore zero for the next invocation
    }
}
__global__ void k_scatter(const int* __restrict__ src, const int* __restrict__ dst, int E) {
    int e = blockIdx.x * blockDim.x + threadIdx.x;
    if (e < E) {
        int d = dst[e];
        int pos = atomicAdd(&g_cur[d], 1);
        g_csrc[pos] = src[e];
        g_cdst[pos] = d;
    }
}

// ================= edge weights (CSR-slot-parallel) =================
__global__ void ew_zr(int E) {
    int i = blockIdx.x * blockDim.x + threadIdx.x;
    if (i >= E) return;
    int s = g_csrc[i], d = g_cdst[i];
    float ez = __expf(lrelu(g_als_z[s] + g_ald_z[d]));
    float er = __expf(lrelu(g_als_r[s] + g_ald_r[d]));
    __half2 p = __floats2half2_rn(ez, er);
    g_ewzr[i] = *(uint32_t*)&p;
}
__global__ void ew_h(int E) {
    int i = blockIdx.x * blockDim.x + threadIdx.x;
    if (i >= E) return;
    int s = g_csrc[i], d = g_cdst[i];
    g_ewh[i] = __float2half(__expf(lrelu(g_als_h[s] + g_ald_h[d])));
}

// ================= fp16 wmma GEMMs =================
#define AH_LD 24
#define BH_LD_ZR 136
#define BH_LD_H 72
#define CS_LD_ZR 132
#define CS_LD_H 68

// gemm_zr: BM=64, BN=128 (z|r interleaved pairs); software-pipelined gmem loads;
// epilogue computes als/ald for z and r (fused node_attn_zr). R14-proven.
__global__ void __launch_bounds__(256)
gemm_zr(const float* __restrict__ A1, const float* __restrict__ A2,
        const float* __restrict__ B1, const float* __restrict__ B2,
        const float* __restrict__ az_s, const float* __restrict__ az_d,
        const float* __restrict__ ar_s, const float* __restrict__ ar_d, int n)
{
    __shared__ __half Ah[64 * AH_LD];
    __shared__ __half Bh[16 * BH_LD_ZR];
    __shared__ float Cs[64 * CS_LD_ZR];

    int tid = threadIdx.x, warp = tid >> 5;
    int warp_m = warp >> 1, warp_n = warp & 1;
    int row0 = blockIdx.x * 64;

    wmma::fragment<wmma::accumulator, 16, 16, 16, float> acc[4];
#pragma unroll
    for (int j = 0; j < 4; j++) wmma::fill_fragment(acc[j], 0.f);

    int a_row = tid >> 2;
    int a_kg = (tid & 3) * 4;
    int b_kk = tid >> 4;
    int b_q = tid & 15;
    int grow = row0 + a_row;

    float4 pa, pbz, pbr;

#define LOADT(K0)                                                              \
    {                                                                          \
        int k = (K0) + a_kg;                                                   \
        pa = make_float4(0.f, 0.f, 0.f, 0.f);                                  \
        if (grow < n) {                                                        \
            if (k < FIN) pa = *(const float4*)(A1 + (size_t)grow * FIN + k);   \
            else         pa = *(const float4*)(A2 + (size_t)grow * C + (k - FIN)); \
        }                                                                      \
        pbz = *(const float4*)(B1 + (size_t)((K0) + b_kk) * C + b_q * 4);      \
        pbr = *(const float4*)(B2 + (size_t)((K0) + b_kk) * C + b_q * 4);      \
    }
#define STORET()                                                               \
    {                                                                          \
        __half2* pap = (__half2*)(Ah + a_row * AH_LD + a_kg);                  \
        pap[0] = __floats2half2_rn(pa.x, pa.y);                                \
        pap[1] = __floats2half2_rn(pa.z, pa.w);                                \
        __half2* pbp = (__half2*)(Bh + b_kk * BH_LD_ZR + b_q * 8);             \
        pbp[0] = __floats2half2_rn(pbz.x, pbz.y);                              \
        pbp[1] = __floats2half2_rn(pbr.x, pbr.y);                              \
        pbp[2] = __floats2half2_rn(pbz.z, pbz.w);                              \
        pbp[3] = __floats2half2_rn(pbr.z, pbr.w);                              \
    }

    LOADT(0);
    STORET();
    __syncthreads();

    const int nIt = D / 16;  // 12
    for (int it = 0; it < nIt; it++) {
        if (it + 1 < nIt) LOADT((it + 1) * 16);

        wmma::fragment<wmma::matrix_a, 16, 16, 16, __half, wmma::row_major> fa;
        wmma::load_matrix_sync(fa, Ah + warp_m * 16 * AH_LD, AH_LD);
#pragma unroll
        for (int j = 0; j < 4; j++) {
            wmma::fragment<wmma::matrix_b, 16, 16, 16, __half, wmma::row_major> fb;
            wmma::load_matrix_sync(fb, Bh + warp_n * 64 + j * 16, BH_LD_ZR);
            wmma::mma_sync(acc[j], fa, fb, acc[j]);
        }
        __syncthreads();
        if (it + 1 < nIt) {
            STORET();
            __syncthreads();
        }
    }
#undef LOADT
#undef STORET

#pragma unroll
    for (int j = 0; j < 4; j++)
        wmma::store_matrix_sync(Cs + warp_m * 16 * CS_LD_ZR + warp_n * 64 + j * 16,
                                acc[j], CS_LD_ZR, wmma::mem_row_major);
    __syncthreads();
    {
        int r = tid >> 2;
        int grow2 = row0 + r;
        float sz = 0.f, dz = 0.f, sr = 0.f, dr = 0.f;
#pragma unroll
        for (int qq = 0; qq < 4; qq++) {
            int q = (tid & 3) * 4 + qq;          // q-group: phys cols 8q..8q+7
            float4 f0 = *(const float4*)(Cs + r * CS_LD_ZR + 8 * q);
            float4 f1 = *(const float4*)(Cs + r * CS_LD_ZR + 8 * q + 4);
            // z cols 4q..4q+3 = f0.x,f0.y,f1.x,f1.y ; r cols = f0.z,f0.w,f1.z,f1.w
            sz += f0.x * __ldg(az_s + 4 * q) + f0.y * __ldg(az_s + 4 * q + 1)
                + f1.x * __ldg(az_s + 4 * q + 2) + f1.y * __ldg(az_s + 4 * q + 3);
            dz += f0.x * __ldg(az_d + 4 * q) + f0.y * __ldg(az_d + 4 * q + 1)
                + f1.x * __ldg(az_d + 4 * q + 2) + f1.y * __ldg(az_d + 4 * q + 3);
            sr += f0.z * __ldg(ar_s + 4 * q) + f0.w * __ldg(ar_s + 4 * q + 1)
                + f1.z * __ldg(ar_s + 4 * q + 2) + f1.w * __ldg(ar_s + 4 * q + 3);
            dr += f0.z * __ldg(ar_d + 4 * q) + f0.w * __ldg(ar_d + 4 * q + 1)
                + f1.z * __ldg(ar_d + 4 * q + 2) + f1.w * __ldg(ar_d + 4 * q + 3);
            if (grow2 < n) {
                __half2 h0 = __floats2half2_rn(f0.x, f0.y);
                __half2 h1 = __floats2half2_rn(f0.z, f0.w);
                __half2 h2 = __floats2half2_rn(f1.x, f1.y);
                __half2 h3 = __floats2half2_rn(f1.z, f1.w);
                uint4 pk;
                pk.x = *(uint32_t*)&h0; pk.y = *(uint32_t*)&h1;
                pk.z = *(uint32_t*)&h2; pk.w = *(uint32_t*)&h3;
                *(uint4*)(g_hzr + (size_t)grow2 * 128 + 8 * q) = pk;
            }
        }
        sz += __shfl_xor_sync(0xffffffffu, sz, 1);
        sz += __shfl_xor_sync(0xffffffffu, sz, 2);
        dz += __shfl_xor_sync(0xffffffffu, dz, 1);
        dz += __shfl_xor_sync(0xffffffffu, dz, 2);
        sr += __shfl_xor_sync(0xffffffffu, sr, 1);
        sr += __shfl_xor_sync(0xffffffffu, sr, 2);
        dr += __shfl_xor_sync(0xffffffffu, dr, 1);
        dr += __shfl_xor_sync(0xffffffffu, dr, 2);
        if ((tid & 3) == 0 && grow2 < n) {
            g_als_z[grow2] = sz; g_ald_z[grow2] = dz;
            g_als_r[grow2] = sr; g_ald_r[grow2] = dr;
        }
    }
}

// gemm_hx: X (n x 128) @ Wh[0:128] -> fp32 partial g_hhp (side stream).
__global__ void __launch_bounds__(256)
gemm_hx(const float* __restrict__ A1, const float* __restrict__ B1, int n)
{
    __shared__ __half Ah[64 * AH_LD];
    __shared__ __half Bh[16 * BH_LD_H];

    int tid = threadIdx.x, warp = tid >> 5;
    int warp_m = warp >> 1, warp_n = warp & 1;
    int row0 = blockIdx.x * 64;

    wmma::fragment<wmma::accumulator, 16, 16, 16, float> acc[2];
#pragma unroll
    for (int j = 0; j < 2; j++) wmma::fill_fragment(acc[j], 0.f);

    int a_row = tid >> 2;
    int a_kg = (tid & 3) * 4;
    int b_kk = tid >> 4;
    int b_col = (tid & 15) * 4;
    int grow = row0 + a_row;

    for (int k0 = 0; k0 < FIN; k0 += 16) {
        {
            float4 v = make_float4(0.f, 0.f, 0.f, 0.f);
            if (grow < n) v = *(const float4*)(A1 + (size_t)grow * FIN + k0 + a_kg);
            __half2* pa = (__half2*)(Ah + a_row * AH_LD + a_kg);
            pa[0] = __floats2half2_rn(v.x, v.y);
            pa[1] = __floats2half2_rn(v.z, v.w);
        }
        {
            float4 v = *(const float4*)(B1 + (size_t)(k0 + b_kk) * C + b_col);
            __half2* pb = (__half2*)(Bh + b_kk * BH_LD_H + b_col);
            pb[0] = __floats2half2_rn(v.x, v.y);
            pb[1] = __floats2half2_rn(v.z, v.w);
        }
        __syncthreads();

        wmma::fragment<wmma::matrix_a, 16, 16, 16, __half, wmma::row_major> fa;
        wmma::load_matrix_sync(fa, Ah + warp_m * 16 * AH_LD, AH_LD);
#pragma unroll
        for (int j = 0; j < 2; j++) {
            wmma::fragment<wmma::matrix_b, 16, 16, 16, __half, wmma::row_major> fb;
            wmma::load_matrix_sync(fb, Bh + warp_n * 32 + j * 16, BH_LD_H);
            wmma::mma_sync(acc[j], fa, fb, acc[j]);
        }
        __syncthreads();
    }
#pragma unroll
    for (int j = 0; j < 2; j++)
        wmma::store_matrix_sync(g_hhp + (size_t)(row0 + warp_m * 16) * C + warp_n * 32 + j * 16,
                                acc[j], C, wmma::mem_row_major);
}

// gemm_hhr: g_HR @ Wh[128:192] + g_hhp -> g_hh; epilogue computes als_h/ald_h.
__global__ void __launch_bounds__(256)
gemm_hhr(const float* __restrict__ B1,
         const float* __restrict__ ah_s, const float* __restrict__ ah_d, int n)
{
    __shared__ __half Ah[64 * AH_LD];
    __shared__ __half Bh[16 * BH_LD_H];
    __shared__ float Cs[64 * CS_LD_H];

    int tid = threadIdx.x, warp = tid >> 5;
    int warp_m = warp >> 1, warp_n = warp & 1;
    int row0 = blockIdx.x * 64;

    wmma::fragment<wmma::accumulator, 16, 16, 16, float> acc[2];
#pragma unroll
    for (int j = 0; j < 2; j++) wmma::fill_fragment(acc[j], 0.f);

    int a_row = tid >> 2;
    int a_kg = (tid & 3) * 4;
    int b_kk = tid >> 4;
    int b_col = (tid & 15) * 4;
    int grow = row0 + a_row;

    for (int k0 = 0; k0 < C; k0 += 16) {
        {
            uint2 raw = make_uint2(0u, 0u);
            if (grow < n) raw = *(const uint2*)(g_HR + (size_t)grow * C + k0 + a_kg);
            __half2* pa = (__half2*)(Ah + a_row * AH_LD + a_kg);
            pa[0] = *(__half2*)&raw.x;
            pa[1] = *(__half2*)&raw.y;
        }
        {
            float4 v = *(const float4*)(B1 + (size_t)(FIN + k0 + b_kk) * C + b_col);
            __half2* pb = (__half2*)(Bh + b_kk * BH_LD_H + b_col);
            pb[0] = __floats2half2_rn(v.x, v.y);
            pb[1] = __floats2half2_rn(v.z, v.w);
        }
        __syncthreads();

        wmma::fragment<wmma::matrix_a, 16, 16, 16, __half, wmma::row_major> fa;
        wmma::load_matrix_sync(fa, Ah + warp_m * 16 * AH_LD, AH_LD);
#pragma unroll
        for (int j = 0; j < 2; j++) {
            wmma::fragment<wmma::matrix_b, 16, 16, 16, __half, wmma::row_major> fb;
            wmma::load_matrix_sync(fb, Bh + warp_n * 32 + j * 16, BH_LD_H);
            wmma::mma_sync(acc[j], fa, fb, acc[j]);
        }
        __syncthreads();
    }

#pragma unroll
    for (int j = 0; j < 2; j++)
        wmma::store_matrix_sync(Cs + warp_m * 16 * CS_LD_H + warp_n * 32 + j * 16,
                                acc[j], CS_LD_H, wmma::mem_row_major);
    __syncthreads();
    {
        int r = tid >> 2, c0 = (tid & 3) * 16;
        int grow2 = row0 + r;
        float s = 0.f, d = 0.f;
#pragma unroll
        for (int c = 0; c < 16; c += 8) {
            float4 f0 = *(const float4*)(Cs + r * CS_LD_H + c0 + c);
            float4 f1 = *(const float4*)(Cs + r * CS_LD_H + c0 + c + 4);
            float4 p0 = make_float4(0.f, 0.f, 0.f, 0.f), p1 = p0;
            if (grow2 < n) {
                p0 = *(const float4*)(g_hhp + (size_t)grow2 * C + c0 + c);
                p1 = *(const float4*)(g_hhp + (size_t)grow2 * C + c0 + c + 4);
            }
            float v0 = f0.x + p0.x, v1 = f0.y + p0.y, v2 = f0.z + p0.z, v3 = f0.w + p0.w;
            float v4 = f1.x + p1.x, v5 = f1.y + p1.y, v6 = f1.z + p1.z, v7 = f1.w + p1.w;
            int cc = c0 + c;
            s += v0 * __ldg(ah_s + cc) + v1 * __ldg(ah_s + cc + 1)
               + v2 * __ldg(ah_s + cc + 2) + v3 * __ldg(ah_s + cc + 3)
               + v4 * __ldg(ah_s + cc + 4) + v5 * __ldg(ah_s + cc + 5)
               + v6 * __ldg(ah_s + cc + 6) + v7 * __ldg(ah_s + cc + 7);
            d += v0 * __ldg(ah_d + cc) + v1 * __ldg(ah_d + cc + 1)
               + v2 * __ldg(ah_d + cc + 2) + v3 * __ldg(ah_d + cc + 3)
               + v4 * __ldg(ah_d + cc + 4) + v5 * __ldg(ah_d + cc + 5)
               + v6 * __ldg(ah_d + cc + 6) + v7 * __ldg(ah_d + cc + 7);
            if (grow2 < n) {
                __half2 h0 = __floats2half2_rn(v0, v1);
                __half2 h1 = __floats2half2_rn(v2, v3);
                __half2 h2 = __floats2half2_rn(v4, v5);
                __half2 h3 = __floats2half2_rn(v6, v7);
                uint4 pk;
                pk.x = *(uint32_t*)&h0; pk.y = *(uint32_t*)&h1;
                pk.z = *(uint32_t*)&h2; pk.w = *(uint32_t*)&h3;
                *(uint4*)(g_hh + (size_t)grow2 * C + cc) = pk;
            }
        }
        s += __shfl_xor_sync(0xffffffffu, s, 1);
        s += __shfl_xor_sync(0xffffffffu, s, 2);
        d += __shfl_xor_sync(0xffffffffu, d, 1);
        d += __shfl_xor_sync(0xffffffffu, d, 2);
        if ((tid & 3) == 0 && grow2 < n) { g_als_h[grow2] = s; g_ald_h[grow2] = d; }
    }
}

// ================= fused per-dst accumulation (unroll-4) =====================
__global__ void zr_node(const float* __restrict__ H,
                        const float* __restrict__ bz, const float* __restrict__ br, int n)
{
    int d = (blockIdx.x * blockDim.x + threadIdx.x) >> 5;
    if (d >= n) return;
    int l = threadIdx.x & 31;

    float ez = 0.f, er = 0.f;
    if (l == 0)  ez = __expf(lrelu(g_als_z[d] + g_ald_z[d]));
    if (l == 16) er = __expf(lrelu(g_als_r[d] + g_ald_r[d]));
    ez = __shfl_sync(0xffffffffu, ez, 0);
    er = __shfl_sync(0xffffffffu, er, 16);

    uint2 raw = *(const uint2*)(g_hzr + (size_t)d * 128 + 4 * l);
    float2 vz = __half22float2(*(__half2*)&raw.x);
    float2 vr = __half22float2(*(__half2*)&raw.y);
    float az0 = vz.x * ez, az1 = vz.y * ez;
    float ar0 = vr.x * er, ar1 = vr.y * er;
    float denz = ez, denr = er;

    int b = g_rs[d], e_end = g_rs[d + 1];
    int i = b;
    for (; i + 3 < e_end; i += 4) {
        int s0 = g_csrc[i], s1 = g_csrc[i + 1], s2 = g_csrc[i + 2], s3 = g_csrc[i + 3];
        uint32_t w0 = g_ewzr[i], w1 = g_ewzr[i + 1], w2 = g_ewzr[i + 2], w3 = g_ewzr[i + 3];
        uint2 r0 = *(const uint2*)(g_hzr + (size_t)s0 * 128 + 4 * l);
        uint2 r1 = *(const uint2*)(g_hzr + (size_t)s1 * 128 + 4 * l);
        uint2 r2 = *(const uint2*)(g_hzr + (size_t)s2 * 128 + 4 * l);
        uint2 r3 = *(const uint2*)(g_hzr + (size_t)s3 * 128 + 4 * l);
        float2 e0 = __half22float2(*(__half2*)&w0);
        float2 e1 = __half22float2(*(__half2*)&w1);
        float2 e2 = __half22float2(*(__half2*)&w2);
        float2 e3 = __half22float2(*(__half2*)&w3);
        float2 uz0 = __half22float2(*(__half2*)&r0.x), ur0 = __half22float2(*(__half2*)&r0.y);
        float2 uz1 = __half22float2(*(__half2*)&r1.x), ur1 = __half22float2(*(__half2*)&r1.y);
        float2 uz2 = __half22float2(*(__half2*)&r2.x), ur2 = __half22float2(*(__half2*)&r2.y);
        float2 uz3 = __half22float2(*(__half2*)&r3.x), ur3 = __half22float2(*(__half2*)&r3.y);
        az0 += uz0.x * e0.x + uz1.x * e1.x + uz2.x * e2.x + uz3.x * e3.x;
        az1 += uz0.y * e0.x + uz1.y * e1.x + uz2.y * e2.x + uz3.y * e3.x;
        ar0 += ur0.x * e0.y + ur1.x * e1.y + ur2.x * e2.y + ur3.x * e3.y;
        ar1 += ur0.y * e0.y + ur1.y * e1.y + ur2.y * e2.y + ur3.y * e3.y;
        denz += e0.x + e1.x + e2.x + e3.x;
        denr += e0.y + e1.y + e2.y + e3.y;
    }
    for (; i < e_end; i++) {
        int s0 = g_csrc[i];
        uint32_t w0 = g_ewzr[i];
        float2 e0 = __half22float2(*(__half2*)&w0);
        uint2 r0 = *(const uint2*)(g_hzr + (size_t)s0 * 128 + 4 * l);
        float2 uz0 = __half22float2(*(__half2*)&r0.x);
        float2 ur0 = __half22float2(*(__half2*)&r0.y);
        az0 += uz0.x * e0.x; az1 += uz0.y * e0.x;
        ar0 += ur0.x * e0.y; ar1 += ur0.y * e0.y;
        denz += e0.x; denr += e0.y;
    }

    float iz = 1.f / (denz + 1e-16f), ir = 1.f / (denr + 1e-16f);
    float Z0 = sigmoidf_(az0 * iz + __ldg(bz + 2 * l));
    float Z1 = sigmoidf_(az1 * iz + __ldg(bz + 2 * l + 1));
    float R0 = sigmoidf_(ar0 * ir + __ldg(br + 2 * l));
    float R1 = sigmoidf_(ar1 * ir + __ldg(br + 2 * l + 1));
    float2 Hv = *(const float2*)(H + (size_t)d * C + 2 * l);
    *(float2*)(g_Z + (size_t)d * C + 2 * l) = make_float2(Z0, Z1);
    __half2 hr = __floats2half2_rn(Hv.x * R0, Hv.y * R1);
    *(uint32_t*)(g_HR + (size_t)d * C + 2 * l) = *(uint32_t*)&hr;
}

__global__ void h_node(const float* __restrict__ H, const float* __restrict__ bh,
                       float* __restrict__ out, int n)
{
    int d = (blockIdx.x * blockDim.x + threadIdx.x) >> 5;
    if (d >= n) return;
    int l = threadIdx.x & 31;

    float eh = 0.f;
    if (l == 0) eh = __expf(lrelu(g_als_h[d] + g_ald_h[d]));
    eh = __shfl_sync(0xffffffffu, eh, 0);

    uint32_t raw = *(const uint32_t*)(g_hh + (size_t)d * C + 2 * l);
    float2 v = __half22float2(*(__half2*)&raw);
    float a0 = v.x * eh, a1 = v.y * eh;
    float den = eh;

    int b = g_rs[d], e_end = g_rs[d + 1];
    int i = b;
    for (; i + 3 < e_end; i += 4) {
        int s0 = g_csrc[i], s1 = g_csrc[i + 1], s2 = g_csrc[i + 2], s3 = g_csrc[i + 3];
        float eh0 = __half2float(g_ewh[i]);
        float eh1 = __half2float(g_ewh[i + 1]);
        float eh2 = __half2float(g_ewh[i + 2]);
        float eh3 = __half2float(g_ewh[i + 3]);
        uint32_t w0 = *(const uint32_t*)(g_hh + (size_t)s0 * C + 2 * l);
        uint32_t w1 = *(const uint32_t*)(g_hh + (size_t)s1 * C + 2 * l);
        uint32_t w2 = *(const uint32_t*)(g_hh + (size_t)s2 * C + 2 * l);
        uint32_t w3 = *(const uint32_t*)(g_hh + (size_t)s3 * C + 2 * l);
        float2 u0 = __half22float2(*(__half2*)&w0);
        float2 u1 = __half22float2(*(__half2*)&w1);
        float2 u2 = __half22float2(*(__half2*)&w2);
        float2 u3 = __half22float2(*(__half2*)&w3);
        a0 += u0.x * eh0 + u1.x * eh1 + u2.x * eh2 + u3.x * eh3;
        a1 += u0.y * eh0 + u1.y * eh1 + u2.y * eh2 + u3.y * eh3;
        den += eh0 + eh1 + eh2 + eh3;
    }
    for (; i < e_end; i++) {
        int s0 = g_csrc[i];
        float eh0 = __half2float(g_ewh[i]);
        uint32_t w0 = *(const uint32_t*)(g_hh + (size_t)s0 * C + 2 * l);
        float2 u0 = __half22float2(*(__half2*)&w0);
        a0 += u0.x * eh0; a1 += u0.y * eh0;
        den += eh0;
    }

    float inv = 1.f / (den + 1e-16f);
    float ht0 = tanhf(a0 * inv + __ldg(bh + 2 * l));
    float ht1 = tanhf(a1 * inv + __ldg(bh + 2 * l + 1));
    float2 Zv = *(const float2*)(g_Z + (size_t)d * C + 2 * l);
    float2 Hv = *(const float2*)(H + (size_t)d * C + 2 * l);
    float o0 = Zv.x * Hv.x + (1.f - Zv.x) * ht0;
    float o1 = Zv.y * Hv.y + (1.f - Zv.y) * ht1;
    *(float2*)(out + (size_t)d * C + 2 * l) = make_float2(o0, o1);
}

// ---------------- launch ----------------
extern "C" void kernel_launch(void* const* d_in, const int* in_sizes, int n_in,
                              void* d_out, int out_size)
{
    const float* X    = (const float*)d_in[0];
    const int*   ei   = (const int*)  d_in[1];
    const float* H    = (const float*)d_in[2];
    const float* Wz   = (const float*)d_in[3];
    const float* az_s = (const float*)d_in[4];
    const float* az_d = (const float*)d_in[5];
    const float* bz   = (const float*)d_in[6];
    const float* Wr   = (const float*)d_in[7];
    const float* ar_s = (const float*)d_in[8];
    const float* ar_d = (const float*)d_in[9];
    const float* br   = (const float*)d_in[10];
    const float* Wh   = (const float*)d_in[11];
    const float* ah_s = (const float*)d_in[12];
    const float* ah_d = (const float*)d_in[13];
    const float* bh   = (const float*)d_in[14];

    int n = in_sizes[0] / FIN;
    int E = in_sizes[1] / 2;
    const int* src = ei;
    const int* dst = ei + E;

    int nb = (n + SCAN_B - 1) / SCAN_B;
    int gemm_blocks = (n + 63) / 64;
    int warp_blocks = (n * 32 + 255) / 256;
    int eth = (E + 255) / 256;

    static cudaStream_t s_side = nullptr;
    static cudaEvent_t s_fork = nullptr, s_csr = nullptr, s_hx = nullptr;
    if (s_side == nullptr) {
        cudaStreamCreateWithFlags(&s_side, cudaStreamNonBlocking);
        cudaEventCreateWithFlags(&s_fork, cudaEventDisableTiming);
        cudaEventCreateWithFlags(&s_csr, cudaEventDisableTiming);
        cudaEventCreateWithFlags(&s_hx, cudaEventDisableTiming);
    }

    cudaEventRecord(s_fork, 0);
    cudaStreamWaitEvent(s_side, s_fork, 0);

    k_count<<<eth, 256, 0, s_side>>>(dst, E);                 // 0 (side)
    k_scan1<<<nb, SCAN_B, 0, s_side>>>(n);                    // 1 (side)
    k_scan2<<<1, 512, 0, s_side>>>(nb, n);                    // 2 (side)
    gemm_zr<<<gemm_blocks, 256>>>(X, H, Wz, Wr,
                                  az_s, az_d, ar_s, ar_d, n); // 3 (main) <- profiled
    k_scan3<<<nb, SCAN_B, 0, s_side>>>(n);                    // 4 (side)
    k_scatter<<<eth, 256, 0, s_side>>>(src, dst, E);          // 5 (side)
    cudaEventRecord(s_csr, s_side);
    gemm_hx<<<gemm_blocks, 256, 0, s_side>>>(X, Wh, n);       // 6 (side)
    cudaEventRecord(s_hx, s_side);

    cudaStreamWaitEvent(0, s_csr, 0);                         // need CSR + als_zr
    ew_zr<<<eth, 256>>>(E);
    zr_node<<<warp_blocks, 256>>>(H, bz, br, n);

    cudaStreamWaitEvent(0, s_hx, 0);                          // need X@Wh partial
    gemm_hhr<<<gemm_blocks, 256>>>(Wh, ah_s, ah_d, n);
    ew_h<<<eth, 256>>>(E);
    h_node<<<warp_blocks, 256>>>(H, bh, (float*)d_out, n);
}